// round 14
// baseline (speedup 1.0000x reference)
#include <cuda_runtime.h>
#include <cuda_bf16.h>
#include <cstdint>

// Problem constants
#define NVEC   65536      // N = B*H*W = 16*64*64
#define KCODE  1024
#define DIM    64
#define HW     4096       // H*W
#define CHW    262144     // C*H*W

// Output layout (concatenated in reference return order, all fp32)
#define QUANT_OFF 0
#define LOSS_OFF  4194304
#define PERP_OFF  4194305
#define NCS_OFF   4194306
#define EMAW_OFF  4195330
#define EMBW_OFF  4260866

#define NTILES   1024     // 64-row work tiles
#define GRID_ARG 592      // 148 SMs * 4 blocks
#define UQGRID   512      // fused update2+quant blocks (all resident)

// Scratch (device globals — no allocation allowed)
__device__ int   g_idx[NVEC];
__device__ __align__(16) float g_Wt[DIM * KCODE];     // Wt[d][k]
__device__ float g_w2[KCODE];
__device__ int   g_counts[KCODE];
__device__ __align__(16) float g_dw[KCODE * DIM];
__device__ __align__(16) float g_embed[KCODE * DIM];  // aligned copy of new codebook
__device__ float g_inv[KCODE];                        // 1/normalized[k]
__device__ float g_loss;
__device__ unsigned int g_done;
__device__ unsigned int g_upd;
__device__ unsigned int g_argdone;
__device__ int   g_tile;

// ---------------------------------------------------------------------------
// Kernel A: prep — transpose W, ||w||^2, zero accumulators, reset counters
// ---------------------------------------------------------------------------
__global__ void prep_kernel(const float* __restrict__ W) {
    int i = blockIdx.x * 256 + threadIdx.x;   // 0..65535
    g_dw[i] = 0.f;
    int d = i >> 10;
    int k = i & 1023;
    g_Wt[i] = W[k * DIM + d];
    if (i < KCODE) {
        g_counts[i] = 0;
        const float* row = W + i * DIM;
        float s = 0.f;
        #pragma unroll
        for (int dd = 0; dd < DIM; ++dd) {
            float v = row[dd];
            s = fmaf(v, v, s);
        }
        g_w2[i] = s;
    }
    if (i == 0) { g_loss = 0.f; g_tile = 0; g_done = 0u; g_upd = 0u; g_argdone = 0u; }
}

// ---------------------------------------------------------------------------
// Kernel B: persistent fused distance-GEMM + argmin + counts + dw scatter,
// with update1 (codebook stats) executed by the LAST block to finish — its
// work hides in the drain shadow of the other 591 blocks.
// Core geometry (proven R11): 128 threads; 64 rows x 128-code tiles; 8x8
// thread tile; 48 KB smem exactly; tile index bounced through xs[0][0].
// ---------------------------------------------------------------------------
__global__ void __launch_bounds__(128) argmin_kernel(const float* __restrict__ in,
                                                     const float* __restrict__ ecs,
                                                     float* __restrict__ out) {
    __shared__ __align__(16) float xs[DIM][64];      // 16 KB, xs[d][row]
    __shared__ union USm {
        float ws[DIM][128];                          // 32 KB, ws[d][k]
        struct { float rv[64][16]; int ri[64][16]; } red;   // 8 KB overlay
    } u;

    const int tid = threadIdx.x;     // 0..127
    const int tx  = tid & 15;        // code group (16 x 8 codes)
    const int ty  = tid >> 4;        // row group  (8 x 8 rows)

    for (;;) {
        if (tid == 0)
            *reinterpret_cast<volatile int*>(&xs[0][0]) = atomicAdd(&g_tile, 1);
        __syncthreads();
        const int tile = *reinterpret_cast<volatile int*>(&xs[0][0]);
        __syncthreads();              // all threads read tile before xs overwrite
        if (tile >= NTILES) break;

        const int n0  = tile * 64;
        const int b   = n0 >> 12;        // 4096 rows per image
        const int hw0 = n0 & 4095;

        // --- load x tile: xs[d][c] = in[b*CHW + d*HW + hw0 + c], coalesced
        const float* src = in + (size_t)b * CHW + hw0;
        #pragma unroll
        for (int i = 0; i < 8; ++i) {
            int fidx = i * 128 + tid;          // float4 index over 64x16
            int d  = fidx >> 4;
            int c4 = fidx & 15;
            float4 v = __ldg(reinterpret_cast<const float4*>(src + d * HW + c4 * 4));
            *reinterpret_cast<float4*>(&xs[d][c4 * 4]) = v;
        }

        float minv[8];
        int   mink[8];
        #pragma unroll
        for (int r = 0; r < 8; ++r) { minv[r] = 3.4e38f; mink[r] = 0; }

        __syncthreads();

        for (int t8 = 0; t8 < 8; ++t8) {
            // load 64x128 code tile (g_Wt is [d][k] -> coalesced)
            #pragma unroll
            for (int i = 0; i < 16; ++i) {
                int fidx = i * 128 + tid;      // float4 index over 64x32
                int d  = fidx >> 5;
                int c4 = fidx & 31;
                float4 v = __ldg(reinterpret_cast<const float4*>(
                                 &g_Wt[d * KCODE + t8 * 128 + c4 * 4]));
                *reinterpret_cast<float4*>(&u.ws[d][c4 * 4]) = v;
            }
            __syncthreads();

            float acc[8][8];
            #pragma unroll
            for (int r = 0; r < 8; ++r)
                #pragma unroll
                for (int j = 0; j < 8; ++j) acc[r][j] = 0.f;

            #pragma unroll 2
            for (int d = 0; d < DIM; ++d) {
                float4 a0 = *reinterpret_cast<const float4*>(&xs[d][ty * 8]);
                float4 a1 = *reinterpret_cast<const float4*>(&xs[d][ty * 8 + 4]);
                float4 b0 = *reinterpret_cast<const float4*>(&u.ws[d][tx * 8]);
                float4 b1 = *reinterpret_cast<const float4*>(&u.ws[d][tx * 8 + 4]);
                float ar[8] = {a0.x, a0.y, a0.z, a0.w, a1.x, a1.y, a1.z, a1.w};
                float br[8] = {b0.x, b0.y, b0.z, b0.w, b1.x, b1.y, b1.z, b1.w};
                #pragma unroll
                for (int r = 0; r < 8; ++r)
                    #pragma unroll
                    for (int j = 0; j < 8; ++j)
                        acc[r][j] = fmaf(ar[r], br[j], acc[r][j]);
            }

            // epilogue: dist = w2 - 2*dot (x^2 per-row constant, argmin-invariant)
            #pragma unroll
            for (int j = 0; j < 8; ++j) {
                int kg = t8 * 128 + tx * 8 + j;
                float w2v = __ldg(&g_w2[kg]);
                #pragma unroll
                for (int r = 0; r < 8; ++r) {
                    float v = fmaf(-2.f, acc[r][j], w2v);
                    if (v < minv[r]) { minv[r] = v; mink[r] = kg; }
                }
            }
            __syncthreads();   // before overwriting ws / red
        }

        // --- cross-thread reduction (16 candidates per row)
        #pragma unroll
        for (int r = 0; r < 8; ++r) {
            int row = ty * 8 + r;
            u.red.rv[row][tx] = minv[r];
            u.red.ri[row][tx] = mink[r];
        }
        __syncthreads();

        if (tid < 64) {
            float bv = u.red.rv[tid][0];
            int   bi = u.red.ri[tid][0];
            #pragma unroll
            for (int t = 1; t < 16; ++t) {
                float v  = u.red.rv[tid][t];
                int   ii = u.red.ri[tid][t];
                if (v < bv || (v == bv && ii < bi)) { bv = v; bi = ii; }
            }
            g_idx[n0 + tid] = bi;
            atomicAdd(&g_counts[bi], 1);
            u.red.ri[tid][0] = bi;     // publish for dw scatter
        }
        __syncthreads();

        // --- dw scatter: dw[k][d] += x[n][d] (conflict-free smem reads)
        {
            int row   = tid & 63;
            int dbase = (tid >> 6) * 32;
            int kk = u.red.ri[row][0];
            float* dst = &g_dw[kk * DIM + dbase];
            #pragma unroll
            for (int i = 0; i < 32; ++i)
                atomicAdd(&dst[i], xs[dbase + i][row]);
        }
        __syncthreads();   // protect xs / red before next tile
    }

    // ----- update1 in the LAST block to arrive (counts are all published) ---
    __threadfence();
    if (tid == 0)
        *reinterpret_cast<volatile int*>(&xs[0][0]) =
            (atomicAdd(&g_argdone, 1u) == GRID_ARG - 1) ? 1 : 0;
    __syncthreads();
    if (!*reinterpret_cast<volatile int*>(&xs[0][0])) return;

    {
        const int lane = tid & 31, w = tid >> 5;
        float ncsv[8];
        float v1 = 0.f, v2 = 0.f;
        #pragma unroll
        for (int j = 0; j < 8; ++j) {
            int k = tid + 128 * j;
            float c   = (float)g_counts[k];
            float ncs = ecs[k] * 0.99f + 0.01f * c;
            out[NCS_OFF + k] = ncs;
            ncsv[j] = ncs;
            float p = c * (1.f / (float)NVEC);
            v1 += ncs;
            v2 += p * logf(p + 1e-10f);
        }
        #pragma unroll
        for (int o = 16; o > 0; o >>= 1) {
            v1 += __shfl_down_sync(0xffffffffu, v1, o);
            v2 += __shfl_down_sync(0xffffffffu, v2, o);
        }
        if (lane == 0) { u.red.rv[0][w] = v1; u.red.rv[1][w] = v2; }
        __syncthreads();
        float nsum = u.red.rv[0][0] + u.red.rv[0][1] + u.red.rv[0][2] + u.red.rv[0][3];
        float ent  = u.red.rv[1][0] + u.red.rv[1][1] + u.red.rv[1][2] + u.red.rv[1][3];
        if (tid == 0) out[PERP_OFF] = expf(-ent);
        #pragma unroll
        for (int j = 0; j < 8; ++j) {
            int k = tid + 128 * j;
            float normalized = (ncsv[j] + 1e-5f) / (nsum + 1024.f * 1e-5f) * nsum;
            g_inv[k] = 1.f / normalized;
        }
    }
}

// ---------------------------------------------------------------------------
// Kernel C: fused update2 + quantize + loss. 512 blocks, ALL resident
// (4/SM guaranteed), so the device-wide spin barrier between the embed
// write and the gather phase is deadlock-free.
// ---------------------------------------------------------------------------
__global__ void __launch_bounds__(256, 4) uq_kernel(const float* __restrict__ in,
                                                    const float* __restrict__ emw,
                                                    float* __restrict__ out) {
    const int blk = blockIdx.x;
    const int t   = threadIdx.x;

    // --- phase 1: this block's 128-element slice of the EMA-w/embed update
    if (t < 128) {
        int i = blk * 128 + t;            // 512*128 = 65536, coalesced
        int k = i >> 6;
        float nw = emw[i] * 0.99f + 0.01f * g_dw[i];
        float e  = nw * g_inv[k];
        out[EMAW_OFF + i] = nw;
        out[EMBW_OFF + i] = e;
        g_embed[i] = e;
    }
    __threadfence();
    __syncthreads();
    if (t == 0) {
        atomicAdd(&g_upd, 1u);
        while (atomicAdd(&g_upd, 0u) < (unsigned)UQGRID) __nanosleep(128);
    }
    __syncthreads();

    // --- phase 2: quantize two units + loss partials
    float local = 0.f;
    #pragma unroll
    for (int uu = 0; uu < 2; ++uu) {
        int unit = blk * 2 + uu;
        int b  = unit >> 6;
        int d0 = ((unit >> 2) & 15) * 4;
        int hc = unit & 3;
        const size_t pbase = (size_t)b * CHW + (size_t)d0 * HW;
        const int nbase = b * HW;

        int kk[4];
        #pragma unroll
        for (int it = 0; it < 4; ++it)
            kk[it] = g_idx[nbase + hc * 1024 + it * 256 + t];
        float4 q[4];
        #pragma unroll
        for (int it = 0; it < 4; ++it)
            q[it] = *reinterpret_cast<const float4*>(&g_embed[kk[it] * DIM + d0]);

        #pragma unroll
        for (int it = 0; it < 4; ++it) {
            int hw = hc * 1024 + it * 256 + t;
            float qa[4] = {q[it].x, q[it].y, q[it].z, q[it].w};
            #pragma unroll
            for (int j = 0; j < 4; ++j) {
                size_t off = pbase + (size_t)j * HW + hw;
                float x = in[off];
                out[QUANT_OFF + off] = qa[j];   // x + (q - x) == q
                float diff = x - qa[j];
                local = fmaf(diff, diff, local);
            }
        }
    }

    #pragma unroll
    for (int o = 16; o > 0; o >>= 1)
        local += __shfl_down_sync(0xffffffff, local, o);
    __shared__ float wsum[8];
    if ((t & 31) == 0) wsum[t >> 5] = local;
    __syncthreads();
    if (t == 0) {
        float s = 0.f;
        #pragma unroll
        for (int i = 0; i < 8; ++i) s += wsum[i];
        atomicAdd(&g_loss, s);
        __threadfence();
        unsigned int ticket = atomicAdd(&g_done, 1u);
        if (ticket == UQGRID - 1) {
            float total = atomicAdd(&g_loss, 0.f);   // atomic read after all adds
            out[LOSS_OFF] = 0.25f * total * (1.f / (float)(NVEC * DIM));
        }
    }
}

extern "C" void kernel_launch(void* const* d_in, const int* in_sizes, int n_in,
                              void* d_out, int out_size) {
    const float* in  = (const float*)d_in[0];  // [16,64,64,64]
    const float* W   = (const float*)d_in[1];  // [1024,64]
    const float* ecs = (const float*)d_in[2];  // [1024]
    const float* emw = (const float*)d_in[3];  // [1024,64]
    float* out = (float*)d_out;

    prep_kernel<<<256, 256>>>(W);
    argmin_kernel<<<GRID_ARG, 128>>>(in, ecs, out);
    uq_kernel<<<UQGRID, 256>>>(in, emw, out);
}

// round 15
// speedup vs baseline: 1.2645x; 1.2645x over previous
#include <cuda_runtime.h>
#include <cuda_bf16.h>
#include <cstdint>

// Problem constants
#define NVEC   65536      // N = B*H*W = 16*64*64
#define KCODE  1024
#define DIM    64
#define HW     4096       // H*W
#define CHW    262144     // C*H*W

// Output layout (concatenated in reference return order, all fp32)
#define QUANT_OFF 0
#define LOSS_OFF  4194304
#define PERP_OFF  4194305
#define NCS_OFF   4194306
#define EMAW_OFF  4195330
#define EMBW_OFF  4260866

#define NTILES   1024     // 64-row work tiles
#define GRID_ARG 592      // 148 SMs * 4 blocks

// Scratch (device globals — no allocation allowed)
__device__ int   g_idx[NVEC];
__device__ __align__(16) float g_Wt[DIM * KCODE];     // Wt[d][k]
__device__ float g_w2[KCODE];
__device__ int   g_counts[KCODE];
__device__ __align__(16) float g_dw[KCODE * DIM];
__device__ __align__(16) float g_embed[KCODE * DIM];  // aligned copy of new codebook
__device__ float g_inv[KCODE];                        // 1/normalized[k]
__device__ float g_loss;
__device__ int   g_tile;

// ---------------------------------------------------------------------------
// Kernel A: prep — transpose W, ||w||^2, zero accumulators, reset tile counter
// ---------------------------------------------------------------------------
__global__ void prep_kernel(const float* __restrict__ W) {
    int i = blockIdx.x * 256 + threadIdx.x;   // 0..65535
    g_dw[i] = 0.f;
    int d = i >> 10;
    int k = i & 1023;
    g_Wt[i] = W[k * DIM + d];
    if (i < KCODE) {
        g_counts[i] = 0;
        const float* row = W + i * DIM;
        float s = 0.f;
        #pragma unroll
        for (int dd = 0; dd < DIM; ++dd) {
            float v = row[dd];
            s = fmaf(v, v, s);
        }
        g_w2[i] = s;
    }
    if (i == 0) { g_loss = 0.f; g_tile = 0; }
}

// ---------------------------------------------------------------------------
// Kernel B (champion, ~96% of scalar-FFMA roofline): persistent fused
// distance-GEMM + argmin + counts + dw scatter. 128 threads; block tile
// 64 rows x 128 codes (8 code-tiles); thread tile 8x8 (1 B/MAC smem
// traffic -> FMA-bound). Smem exactly 48 KB; tile index bounced through
// xs[0][0] to stay under the 0xc000 static-smem cap.
// ---------------------------------------------------------------------------
__global__ void __launch_bounds__(128) argmin_kernel(const float* __restrict__ in) {
    __shared__ __align__(16) float xs[DIM][64];      // 16 KB, xs[d][row]
    __shared__ union USm {
        float ws[DIM][128];                          // 32 KB, ws[d][k]
        struct { float rv[64][16]; int ri[64][16]; } red;   // 8 KB overlay
    } u;

    const int tid = threadIdx.x;     // 0..127
    const int tx  = tid & 15;        // code group (16 x 8 codes)
    const int ty  = tid >> 4;        // row group  (8 x 8 rows)

    for (;;) {
        if (tid == 0)
            *reinterpret_cast<volatile int*>(&xs[0][0]) = atomicAdd(&g_tile, 1);
        __syncthreads();
        const int tile = *reinterpret_cast<volatile int*>(&xs[0][0]);
        __syncthreads();              // all threads read tile before xs overwrite
        if (tile >= NTILES) return;

        const int n0  = tile * 64;
        const int b   = n0 >> 12;        // 4096 rows per image
        const int hw0 = n0 & 4095;

        // --- load x tile: xs[d][c] = in[b*CHW + d*HW + hw0 + c], coalesced
        const float* src = in + (size_t)b * CHW + hw0;
        #pragma unroll
        for (int i = 0; i < 8; ++i) {
            int fidx = i * 128 + tid;          // float4 index over 64x16
            int d  = fidx >> 4;
            int c4 = fidx & 15;
            float4 v = __ldg(reinterpret_cast<const float4*>(src + d * HW + c4 * 4));
            *reinterpret_cast<float4*>(&xs[d][c4 * 4]) = v;
        }

        float minv[8];
        int   mink[8];
        #pragma unroll
        for (int r = 0; r < 8; ++r) { minv[r] = 3.4e38f; mink[r] = 0; }

        __syncthreads();

        for (int t8 = 0; t8 < 8; ++t8) {
            // load 64x128 code tile (g_Wt is [d][k] -> coalesced)
            #pragma unroll
            for (int i = 0; i < 16; ++i) {
                int fidx = i * 128 + tid;      // float4 index over 64x32
                int d  = fidx >> 5;
                int c4 = fidx & 31;
                float4 v = __ldg(reinterpret_cast<const float4*>(
                                 &g_Wt[d * KCODE + t8 * 128 + c4 * 4]));
                *reinterpret_cast<float4*>(&u.ws[d][c4 * 4]) = v;
            }
            __syncthreads();

            float acc[8][8];
            #pragma unroll
            for (int r = 0; r < 8; ++r)
                #pragma unroll
                for (int j = 0; j < 8; ++j) acc[r][j] = 0.f;

            #pragma unroll 2
            for (int d = 0; d < DIM; ++d) {
                float4 a0 = *reinterpret_cast<const float4*>(&xs[d][ty * 8]);
                float4 a1 = *reinterpret_cast<const float4*>(&xs[d][ty * 8 + 4]);
                float4 b0 = *reinterpret_cast<const float4*>(&u.ws[d][tx * 8]);
                float4 b1 = *reinterpret_cast<const float4*>(&u.ws[d][tx * 8 + 4]);
                float ar[8] = {a0.x, a0.y, a0.z, a0.w, a1.x, a1.y, a1.z, a1.w};
                float br[8] = {b0.x, b0.y, b0.z, b0.w, b1.x, b1.y, b1.z, b1.w};
                #pragma unroll
                for (int r = 0; r < 8; ++r)
                    #pragma unroll
                    for (int j = 0; j < 8; ++j)
                        acc[r][j] = fmaf(ar[r], br[j], acc[r][j]);
            }

            // epilogue: dist = w2 - 2*dot (x^2 per-row constant, argmin-invariant)
            #pragma unroll
            for (int j = 0; j < 8; ++j) {
                int kg = t8 * 128 + tx * 8 + j;
                float w2v = __ldg(&g_w2[kg]);
                #pragma unroll
                for (int r = 0; r < 8; ++r) {
                    float v = fmaf(-2.f, acc[r][j], w2v);
                    if (v < minv[r]) { minv[r] = v; mink[r] = kg; }
                }
            }
            __syncthreads();   // before overwriting ws / red
        }

        // --- cross-thread reduction (16 candidates per row)
        #pragma unroll
        for (int r = 0; r < 8; ++r) {
            int row = ty * 8 + r;
            u.red.rv[row][tx] = minv[r];
            u.red.ri[row][tx] = mink[r];
        }
        __syncthreads();

        if (tid < 64) {
            float bv = u.red.rv[tid][0];
            int   bi = u.red.ri[tid][0];
            #pragma unroll
            for (int t = 1; t < 16; ++t) {
                float v  = u.red.rv[tid][t];
                int   ii = u.red.ri[tid][t];
                if (v < bv || (v == bv && ii < bi)) { bv = v; bi = ii; }
            }
            g_idx[n0 + tid] = bi;
            atomicAdd(&g_counts[bi], 1);
            u.red.ri[tid][0] = bi;     // publish for dw scatter
        }
        __syncthreads();

        // --- dw scatter: dw[k][d] += x[n][d] (conflict-free smem reads)
        {
            int row   = tid & 63;
            int dbase = (tid >> 6) * 32;
            int kk = u.red.ri[row][0];
            float* dst = &g_dw[kk * DIM + dbase];
            #pragma unroll
            for (int i = 0; i < 32; ++i)
                atomicAdd(&dst[i], xs[dbase + i][row]);
        }
        __syncthreads();   // protect xs / red before next tile
    }
}

// ---------------------------------------------------------------------------
// Kernel C1: scalar codebook stats — ncs, nsum, perplexity, 1/normalized.
// ---------------------------------------------------------------------------
__global__ void update1_kernel(const float* __restrict__ ecs,
                               float* __restrict__ out) {
    int k = threadIdx.x;
    __shared__ float smr[KCODE];

    float c   = (float)g_counts[k];
    float ncs = ecs[k] * 0.99f + 0.01f * c;
    out[NCS_OFF + k] = ncs;

    smr[k] = ncs; __syncthreads();
    for (int s = 512; s > 0; s >>= 1) {
        if (k < s) smr[k] += smr[k + s];
        __syncthreads();
    }
    float nsum = smr[0];
    __syncthreads();

    float p = c * (1.f / (float)NVEC);
    smr[k] = p * logf(p + 1e-10f);
    __syncthreads();
    for (int s = 512; s > 0; s >>= 1) {
        if (k < s) smr[k] += smr[k + s];
        __syncthreads();
    }
    if (k == 0) out[PERP_OFF] = expf(-smr[0]);

    float normalized = (ncs + 1e-5f) / (nsum + 1024.f * 1e-5f) * nsum;
    g_inv[k] = 1.f / normalized;
}

// ---------------------------------------------------------------------------
// Kernel C2: grid-wide coalesced EMA-w + embed write
// ---------------------------------------------------------------------------
__global__ void update2_kernel(const float* __restrict__ emw,
                               float* __restrict__ out) {
    int i = blockIdx.x * 256 + threadIdx.x;   // 0..65535
    int k = i >> 6;
    float nw = emw[i] * 0.99f + 0.01f * g_dw[i];
    float e  = nw * g_inv[k];
    out[EMAW_OFF + i] = nw;
    out[EMBW_OFF + i] = e;
    g_embed[i] = e;            // aligned copy for float4 gathers in quant
}

// ---------------------------------------------------------------------------
// Kernel D: quantize + loss (float4 codebook gathers from aligned g_embed)
// ---------------------------------------------------------------------------
__global__ void quant_kernel(const float* __restrict__ in,
                             float* __restrict__ out) {
    int blk = blockIdx.x;
    int b  = blk >> 6;
    int d0 = ((blk >> 2) & 15) * 4;
    int hc = blk & 3;
    int t  = threadIdx.x;

    const size_t pbase = (size_t)b * CHW + (size_t)d0 * HW;
    const int nbase = b * HW;

    float local = 0.f;
    #pragma unroll
    for (int it = 0; it < 4; ++it) {
        int hw = hc * 1024 + it * 256 + t;
        int kk = g_idx[nbase + hw];
        float4 q = *reinterpret_cast<const float4*>(&g_embed[kk * DIM + d0]);
        float qa[4] = {q.x, q.y, q.z, q.w};
        #pragma unroll
        for (int j = 0; j < 4; ++j) {
            size_t off = pbase + (size_t)j * HW + hw;
            float x = in[off];
            out[QUANT_OFF + off] = qa[j];   // x + (q - x) == q
            float diff = x - qa[j];
            local = fmaf(diff, diff, local);
        }
    }

    #pragma unroll
    for (int o = 16; o > 0; o >>= 1)
        local += __shfl_down_sync(0xffffffff, local, o);
    __shared__ float wsum[8];
    if ((t & 31) == 0) wsum[t >> 5] = local;
    __syncthreads();
    if (t == 0) {
        float s = 0.f;
        #pragma unroll
        for (int i = 0; i < 8; ++i) s += wsum[i];
        atomicAdd(&g_loss, s);
    }
}

__global__ void loss_kernel(float* __restrict__ out) {
    out[LOSS_OFF] = 0.25f * g_loss * (1.f / (float)(NVEC * DIM));
}

extern "C" void kernel_launch(void* const* d_in, const int* in_sizes, int n_in,
                              void* d_out, int out_size) {
    const float* in  = (const float*)d_in[0];  // [16,64,64,64]
    const float* W   = (const float*)d_in[1];  // [1024,64]
    const float* ecs = (const float*)d_in[2];  // [1024]
    const float* emw = (const float*)d_in[3];  // [1024,64]
    float* out = (float*)d_out;

    prep_kernel<<<256, 256>>>(W);
    argmin_kernel<<<GRID_ARG, 128>>>(in);
    update1_kernel<<<1, 1024>>>(ecs, out);
    update2_kernel<<<256, 256>>>(emw, out);
    quant_kernel<<<1024, 256>>>(in, out);
    loss_kernel<<<1, 1>>>(out);
}

// round 16
// speedup vs baseline: 1.3051x; 1.0321x over previous
#include <cuda_runtime.h>
#include <cuda_bf16.h>
#include <cstdint>

// Problem constants
#define NVEC   65536      // N = B*H*W = 16*64*64
#define KCODE  1024
#define DIM    64
#define HW     4096       // H*W
#define CHW    262144     // C*H*W

// Output layout (concatenated in reference return order, all fp32)
#define QUANT_OFF 0
#define LOSS_OFF  4194304
#define PERP_OFF  4194305
#define NCS_OFF   4194306
#define EMAW_OFF  4195330
#define EMBW_OFF  4260866

#define NTILES   1024     // 64-row work tiles
#define GRID_ARG 592      // 148 SMs * 4 blocks

// Scratch (device globals — no allocation allowed)
__device__ int   g_idx[NVEC];
__device__ __align__(16) float g_Wt[DIM * KCODE];     // Wt[d][k]
__device__ float g_w2[KCODE];
__device__ int   g_counts[KCODE];
__device__ __align__(16) float g_dw[KCODE * DIM];
__device__ __align__(16) float g_embed[KCODE * DIM];  // aligned copy of new codebook
__device__ float g_inv[KCODE];                        // 1/normalized[k]
__device__ float g_loss;
__device__ int   g_tile;

// ---------------------------------------------------------------------------
// Kernel A: prep — TILED transpose (coalesced both sides), ||w||^2 from the
// smem tile, zero accumulators. 16 blocks x 256 threads; block kb owns codes
// [kb*64, kb*64+64).
// ---------------------------------------------------------------------------
__global__ void prep_kernel(const float* __restrict__ W) {
    __shared__ float tile[64][65];        // padded: conflict-free transpose
    const int tid = threadIdx.x;
    const int kb  = blockIdx.x;
    const int kbase = kb * 64;

    // coalesced read: W rows are 256 B contiguous
    #pragma unroll
    for (int i = 0; i < 16; ++i) {
        int idx = i * 256 + tid;          // 0..4095
        int row = idx >> 6;               // code within tile
        int col = idx & 63;               // d
        tile[row][col] = W[(kbase + row) * DIM + col];
    }

    // zero g_dw (grid-stride over 16*256 threads) + counts + scalars
    #pragma unroll
    for (int i = 0; i < 16; ++i)
        g_dw[(kb * 256 + tid) * 16 + i] = 0.f;
    __syncthreads();

    // w2: same per-row sequential FMA chain as before (bit-identical)
    if (tid < 64) {
        int k = kbase + tid;
        float s = 0.f;
        #pragma unroll
        for (int dd = 0; dd < DIM; ++dd) {
            float v = tile[tid][dd];
            s = fmaf(v, v, s);
        }
        g_w2[k] = s;
        g_counts[k] = 0;
    }
    if (kb == 0 && tid == 0) { g_loss = 0.f; g_tile = 0; }

    // coalesced transposed write: 64 consecutive k per (d, tile)
    #pragma unroll
    for (int i = 0; i < 16; ++i) {
        int idx = i * 256 + tid;          // 0..4095
        int d  = idx >> 6;
        int kk = idx & 63;
        g_Wt[d * KCODE + kbase + kk] = tile[kk][d];
    }
}

// ---------------------------------------------------------------------------
// Kernel B (champion, ~96% of scalar-FFMA roofline): persistent fused
// distance-GEMM + argmin + counts + dw scatter. 128 threads; block tile
// 64 rows x 128 codes (8 code-tiles); thread tile 8x8 (1 B/MAC smem
// traffic -> FMA-bound). Smem exactly 48 KB; tile index bounced through
// xs[0][0] to stay under the 0xc000 static-smem cap.
// ---------------------------------------------------------------------------
__global__ void __launch_bounds__(128) argmin_kernel(const float* __restrict__ in) {
    __shared__ __align__(16) float xs[DIM][64];      // 16 KB, xs[d][row]
    __shared__ union USm {
        float ws[DIM][128];                          // 32 KB, ws[d][k]
        struct { float rv[64][16]; int ri[64][16]; } red;   // 8 KB overlay
    } u;

    const int tid = threadIdx.x;     // 0..127
    const int tx  = tid & 15;        // code group (16 x 8 codes)
    const int ty  = tid >> 4;        // row group  (8 x 8 rows)

    for (;;) {
        if (tid == 0)
            *reinterpret_cast<volatile int*>(&xs[0][0]) = atomicAdd(&g_tile, 1);
        __syncthreads();
        const int tile = *reinterpret_cast<volatile int*>(&xs[0][0]);
        __syncthreads();              // all threads read tile before xs overwrite
        if (tile >= NTILES) return;

        const int n0  = tile * 64;
        const int b   = n0 >> 12;        // 4096 rows per image
        const int hw0 = n0 & 4095;

        // --- load x tile: xs[d][c] = in[b*CHW + d*HW + hw0 + c], coalesced
        const float* src = in + (size_t)b * CHW + hw0;
        #pragma unroll
        for (int i = 0; i < 8; ++i) {
            int fidx = i * 128 + tid;          // float4 index over 64x16
            int d  = fidx >> 4;
            int c4 = fidx & 15;
            float4 v = __ldg(reinterpret_cast<const float4*>(src + d * HW + c4 * 4));
            *reinterpret_cast<float4*>(&xs[d][c4 * 4]) = v;
        }

        float minv[8];
        int   mink[8];
        #pragma unroll
        for (int r = 0; r < 8; ++r) { minv[r] = 3.4e38f; mink[r] = 0; }

        __syncthreads();

        for (int t8 = 0; t8 < 8; ++t8) {
            // load 64x128 code tile (g_Wt is [d][k] -> coalesced)
            #pragma unroll
            for (int i = 0; i < 16; ++i) {
                int fidx = i * 128 + tid;      // float4 index over 64x32
                int d  = fidx >> 5;
                int c4 = fidx & 31;
                float4 v = __ldg(reinterpret_cast<const float4*>(
                                 &g_Wt[d * KCODE + t8 * 128 + c4 * 4]));
                *reinterpret_cast<float4*>(&u.ws[d][c4 * 4]) = v;
            }
            __syncthreads();

            float acc[8][8];
            #pragma unroll
            for (int r = 0; r < 8; ++r)
                #pragma unroll
                for (int j = 0; j < 8; ++j) acc[r][j] = 0.f;

            #pragma unroll 2
            for (int d = 0; d < DIM; ++d) {
                float4 a0 = *reinterpret_cast<const float4*>(&xs[d][ty * 8]);
                float4 a1 = *reinterpret_cast<const float4*>(&xs[d][ty * 8 + 4]);
                float4 b0 = *reinterpret_cast<const float4*>(&u.ws[d][tx * 8]);
                float4 b1 = *reinterpret_cast<const float4*>(&u.ws[d][tx * 8 + 4]);
                float ar[8] = {a0.x, a0.y, a0.z, a0.w, a1.x, a1.y, a1.z, a1.w};
                float br[8] = {b0.x, b0.y, b0.z, b0.w, b1.x, b1.y, b1.z, b1.w};
                #pragma unroll
                for (int r = 0; r < 8; ++r)
                    #pragma unroll
                    for (int j = 0; j < 8; ++j)
                        acc[r][j] = fmaf(ar[r], br[j], acc[r][j]);
            }

            // epilogue: dist = w2 - 2*dot (x^2 per-row constant, argmin-invariant)
            #pragma unroll
            for (int j = 0; j < 8; ++j) {
                int kg = t8 * 128 + tx * 8 + j;
                float w2v = __ldg(&g_w2[kg]);
                #pragma unroll
                for (int r = 0; r < 8; ++r) {
                    float v = fmaf(-2.f, acc[r][j], w2v);
                    if (v < minv[r]) { minv[r] = v; mink[r] = kg; }
                }
            }
            __syncthreads();   // before overwriting ws / red
        }

        // --- cross-thread reduction (16 candidates per row)
        #pragma unroll
        for (int r = 0; r < 8; ++r) {
            int row = ty * 8 + r;
            u.red.rv[row][tx] = minv[r];
            u.red.ri[row][tx] = mink[r];
        }
        __syncthreads();

        if (tid < 64) {
            float bv = u.red.rv[tid][0];
            int   bi = u.red.ri[tid][0];
            #pragma unroll
            for (int t = 1; t < 16; ++t) {
                float v  = u.red.rv[tid][t];
                int   ii = u.red.ri[tid][t];
                if (v < bv || (v == bv && ii < bi)) { bv = v; bi = ii; }
            }
            g_idx[n0 + tid] = bi;
            atomicAdd(&g_counts[bi], 1);
            u.red.ri[tid][0] = bi;     // publish for dw scatter
        }
        __syncthreads();

        // --- dw scatter: dw[k][d] += x[n][d] (conflict-free smem reads)
        {
            int row   = tid & 63;
            int dbase = (tid >> 6) * 32;
            int kk = u.red.ri[row][0];
            float* dst = &g_dw[kk * DIM + dbase];
            #pragma unroll
            for (int i = 0; i < 32; ++i)
                atomicAdd(&dst[i], xs[dbase + i][row]);
        }
        __syncthreads();   // protect xs / red before next tile
    }
}

// ---------------------------------------------------------------------------
// Kernel C1: scalar codebook stats — ncs, nsum, perplexity, 1/normalized.
// ---------------------------------------------------------------------------
__global__ void update1_kernel(const float* __restrict__ ecs,
                               float* __restrict__ out) {
    int k = threadIdx.x;
    __shared__ float smr[KCODE];

    float c   = (float)g_counts[k];
    float ncs = ecs[k] * 0.99f + 0.01f * c;
    out[NCS_OFF + k] = ncs;

    smr[k] = ncs; __syncthreads();
    for (int s = 512; s > 0; s >>= 1) {
        if (k < s) smr[k] += smr[k + s];
        __syncthreads();
    }
    float nsum = smr[0];
    __syncthreads();

    float p = c * (1.f / (float)NVEC);
    smr[k] = p * logf(p + 1e-10f);
    __syncthreads();
    for (int s = 512; s > 0; s >>= 1) {
        if (k < s) smr[k] += smr[k + s];
        __syncthreads();
    }
    if (k == 0) out[PERP_OFF] = expf(-smr[0]);

    float normalized = (ncs + 1e-5f) / (nsum + 1024.f * 1e-5f) * nsum;
    g_inv[k] = 1.f / normalized;
}

// ---------------------------------------------------------------------------
// Kernel C2: grid-wide coalesced EMA-w + embed write
// ---------------------------------------------------------------------------
__global__ void update2_kernel(const float* __restrict__ emw,
                               float* __restrict__ out) {
    int i = blockIdx.x * 256 + threadIdx.x;   // 0..65535
    int k = i >> 6;
    float nw = emw[i] * 0.99f + 0.01f * g_dw[i];
    float e  = nw * g_inv[k];
    out[EMAW_OFF + i] = nw;
    out[EMBW_OFF + i] = e;
    g_embed[i] = e;            // aligned copy for float4 gathers in quant
}

// ---------------------------------------------------------------------------
// Kernel D: quantize + loss, float4 per thread (4 consecutive hw positions):
// int4 idx load, 4 independent gathers, float4 in-reads/out-writes.
// grid = 1024 (same unit mapping; it-loop replaced by hw vectorization).
// ---------------------------------------------------------------------------
__global__ void quant_kernel(const float* __restrict__ in,
                             float* __restrict__ out) {
    int blk = blockIdx.x;
    int b  = blk >> 6;
    int d0 = ((blk >> 2) & 15) * 4;
    int hc = blk & 3;
    int t  = threadIdx.x;

    const size_t pbase = (size_t)b * CHW + (size_t)d0 * HW;
    const int nbase = b * HW;
    const int hw0 = hc * 1024 + t * 4;       // 4 consecutive hw per thread

    int4 kk4 = *reinterpret_cast<const int4*>(&g_idx[nbase + hw0]);
    int kk[4] = {kk4.x, kk4.y, kk4.z, kk4.w};
    float4 q[4];
    #pragma unroll
    for (int e = 0; e < 4; ++e)
        q[e] = *reinterpret_cast<const float4*>(&g_embed[kk[e] * DIM + d0]);

    float local = 0.f;
    #pragma unroll
    for (int j = 0; j < 4; ++j) {            // dim d0+j
        size_t off = pbase + (size_t)j * HW + hw0;
        float4 x = *reinterpret_cast<const float4*>(&in[off]);
        float xa[4] = {x.x, x.y, x.z, x.w};
        float qa[4];
        #pragma unroll
        for (int e = 0; e < 4; ++e)
            qa[e] = (&q[e].x)[j];
        *reinterpret_cast<float4*>(&out[QUANT_OFF + off]) =
            make_float4(qa[0], qa[1], qa[2], qa[3]);
        #pragma unroll
        for (int e = 0; e < 4; ++e) {
            float diff = xa[e] - qa[e];
            local = fmaf(diff, diff, local);
        }
    }

    #pragma unroll
    for (int o = 16; o > 0; o >>= 1)
        local += __shfl_down_sync(0xffffffff, local, o);
    __shared__ float wsum[8];
    if ((t & 31) == 0) wsum[t >> 5] = local;
    __syncthreads();
    if (t == 0) {
        float s = 0.f;
        #pragma unroll
        for (int i = 0; i < 8; ++i) s += wsum[i];
        atomicAdd(&g_loss, s);
    }
}

__global__ void loss_kernel(float* __restrict__ out) {
    out[LOSS_OFF] = 0.25f * g_loss * (1.f / (float)(NVEC * DIM));
}

extern "C" void kernel_launch(void* const* d_in, const int* in_sizes, int n_in,
                              void* d_out, int out_size) {
    const float* in  = (const float*)d_in[0];  // [16,64,64,64]
    const float* W   = (const float*)d_in[1];  // [1024,64]
    const float* ecs = (const float*)d_in[2];  // [1024]
    const float* emw = (const float*)d_in[3];  // [1024,64]
    float* out = (float*)d_out;

    prep_kernel<<<16, 256>>>(W);
    argmin_kernel<<<GRID_ARG, 128>>>(in);
    update1_kernel<<<1, 1024>>>(ecs, out);
    update2_kernel<<<256, 256>>>(emw, out);
    quant_kernel<<<1024, 256>>>(in, out);
    loss_kernel<<<1, 1>>>(out);
}